// round 1
// baseline (speedup 1.0000x reference)
#include <cuda_runtime.h>
#include <math.h>
#include <float.h>

#define TOKENS 16384
#define HIDDEN 4096
#define NEXP   256
#define NGROUP 8
#define TOPKG  4
#define TOPK   8

// 16 MB scratch for gates [TOKENS, NEXP] (device-global: no allocations allowed)
__device__ float g_gates[TOKENS * NEXP];

// ---------------------------------------------------------------------------
// GEMM: gates[t][e] = sum_k x[t][k] * w[e][k]
// CTA tile 64x64, K-tile 16, 256 threads, 4x4 micro-tile per thread.
// ---------------------------------------------------------------------------
#define BM 64
#define BN 64
#define BK 16

__global__ __launch_bounds__(256) void gemm_gates_kernel(
    const float* __restrict__ x, const float* __restrict__ w)
{
    __shared__ float As[BK][BM];   // As[k][m]
    __shared__ float Bs[BK][BN];   // Bs[k][n]

    const int m0 = blockIdx.y * BM;
    const int n0 = blockIdx.x * BN;
    const int tid = threadIdx.x;
    const int tx = tid & 15;       // n sub
    const int ty = tid >> 4;       // m sub

    // global load mapping: each thread loads one float4 of A and one of B
    const int lr  = tid >> 2;        // 0..63 row within tile
    const int lk4 = (tid & 3) * 4;   // 0,4,8,12 k offset

    const float* xrow = x + (size_t)(m0 + lr) * HIDDEN + lk4;
    const float* wrow = w + (size_t)(n0 + lr) * HIDDEN + lk4;

    float acc[4][4] = {};

    for (int k0 = 0; k0 < HIDDEN; k0 += BK) {
        float4 av = *(const float4*)(xrow + k0);
        float4 bv = *(const float4*)(wrow + k0);
        __syncthreads();
        As[lk4 + 0][lr] = av.x;
        As[lk4 + 1][lr] = av.y;
        As[lk4 + 2][lr] = av.z;
        As[lk4 + 3][lr] = av.w;
        Bs[lk4 + 0][lr] = bv.x;
        Bs[lk4 + 1][lr] = bv.y;
        Bs[lk4 + 2][lr] = bv.z;
        Bs[lk4 + 3][lr] = bv.w;
        __syncthreads();
#pragma unroll
        for (int k = 0; k < BK; k++) {
            float4 a = *(const float4*)&As[k][ty * 4];
            float4 b = *(const float4*)&Bs[k][tx * 4];
            acc[0][0] += a.x * b.x; acc[0][1] += a.x * b.y; acc[0][2] += a.x * b.z; acc[0][3] += a.x * b.w;
            acc[1][0] += a.y * b.x; acc[1][1] += a.y * b.y; acc[1][2] += a.y * b.z; acc[1][3] += a.y * b.w;
            acc[2][0] += a.z * b.x; acc[2][1] += a.z * b.y; acc[2][2] += a.z * b.z; acc[2][3] += a.z * b.w;
            acc[3][0] += a.w * b.x; acc[3][1] += a.w * b.y; acc[3][2] += a.w * b.z; acc[3][3] += a.w * b.w;
        }
    }

#pragma unroll
    for (int i = 0; i < 4; i++) {
        float4 v = make_float4(acc[i][0], acc[i][1], acc[i][2], acc[i][3]);
        *(float4*)&g_gates[(size_t)(m0 + ty * 4 + i) * NEXP + n0 + tx * 4] = v;
    }
}

// ---------------------------------------------------------------------------
// Routing: one warp per token. Replicates reference semantics exactly:
//   orig = sigmoid(gates); scores = orig + bias
//   group_score[g] = top1+top2 of scores within group (32 experts)
//   keep = 4 groups with SMALLEST group_score (ties -> lower group index)
//   s = scores where kept else 0.0
//   inds = 8 entries with SMALLEST s (ties -> lower expert index)
//   sel  = orig[inds]; sel /= (sum(sel)+1e-20); sel *= 2.5
// ---------------------------------------------------------------------------
__global__ __launch_bounds__(256) void route_kernel(
    const float* __restrict__ bias, float* __restrict__ out)
{
    const unsigned FULL = 0xFFFFFFFFu;
    const int warp_in_blk = threadIdx.x >> 5;
    const int lane = threadIdx.x & 31;
    const int t = blockIdx.x * 8 + warp_in_blk;
    if (t >= TOKENS) return;

    // lane handles experts [lane*8, lane*8+8), all within group lane/4
    float orig[8], v[8];
    float m1 = -FLT_MAX, m2 = -FLT_MAX;
#pragma unroll
    for (int j = 0; j < 8; j++) {
        int e = lane * 8 + j;
        float g = g_gates[(size_t)t * NEXP + e];
        // sigmoid (numerically stable, matches jax.nn.sigmoid to ~1 ulp)
        float s;
        if (g >= 0.0f) s = 1.0f / (1.0f + __expf(-g) * 0.0f + expf(-g));  // keep precise expf
        else { float eg = expf(g); s = eg / (1.0f + eg); }
        orig[j] = s;
        float sc = s + bias[e];
        v[j] = sc;
        if (sc > m1) { m2 = m1; m1 = sc; }
        else if (sc > m2) { m2 = sc; }
    }

    // merge top-2 across the 4 lanes of this group (xor butterfly within group)
#pragma unroll
    for (int off = 1; off <= 2; off <<= 1) {
        float o1 = __shfl_xor_sync(FULL, m1, off);
        float o2 = __shfl_xor_sync(FULL, m2, off);
        if (o1 > m1) { m2 = fmaxf(m1, o2); m1 = o1; }
        else         { m2 = fmaxf(m2, o1); }
    }
    float gs = m1 + m2;  // group score, valid on all lanes of the group

    // gather group scores to every lane: gsg = score of group (lane&7)
    float gsg = __shfl_sync(FULL, gs, (lane & 7) * 4);

    // rank of group (lane&7): number of groups strictly smaller, or equal with lower index
    int g = lane & 7;
    int rank = 0;
#pragma unroll
    for (int h = 0; h < 8; h++) {
        float other = __shfl_sync(FULL, gsg, h);
        rank += (other < gsg || (other == gsg && h < g)) ? 1 : 0;
    }
    // kept = among 4 smallest group scores
    unsigned keepmask = __ballot_sync(FULL, (lane < 8) && (rank < TOPKG));
    int mygroup = lane >> 2;
    bool kept = (keepmask >> mygroup) & 1u;

#pragma unroll
    for (int j = 0; j < 8; j++) v[j] = kept ? v[j] : 0.0f;

    // select 8 smallest (value, index) in total order matching jax.lax.top_k(-s)
    int selIdx[8]; float selOrig[8]; float ssum = 0.0f;
#pragma unroll
    for (int k = 0; k < TOPK; k++) {
        float bv = FLT_MAX; int bi = 0x7FFFFFFF; float bo = 0.0f;
#pragma unroll
        for (int j = 0; j < 8; j++) {
            int e = lane * 8 + j;
            if (v[j] < bv || (v[j] == bv && e < bi)) { bv = v[j]; bi = e; bo = orig[j]; }
        }
#pragma unroll
        for (int off = 16; off > 0; off >>= 1) {
            float ov = __shfl_xor_sync(FULL, bv, off);
            int   oi = __shfl_xor_sync(FULL, bi, off);
            float oo = __shfl_xor_sync(FULL, bo, off);
            if (ov < bv || (ov == bv && oi < bi)) { bv = ov; bi = oi; bo = oo; }
        }
        selIdx[k] = bi; selOrig[k] = bo; ssum += bo;
        if ((bi >> 3) == lane) v[bi & 7] = FLT_MAX;  // remove winner
    }

    float inv = 2.5f / (ssum + 1e-20f);
    if (lane < 8) {
        out[(size_t)t * TOPK + lane] = (float)selIdx[lane];                       // inds (as float)
        out[(size_t)TOKENS * TOPK + (size_t)t * TOPK + lane] = selOrig[lane] * inv; // sel
    }
}

extern "C" void kernel_launch(void* const* d_in, const int* in_sizes, int n_in,
                              void* d_out, int out_size)
{
    const float* x    = (const float*)d_in[0];
    const float* w    = (const float*)d_in[1];
    const float* bias = (const float*)d_in[2];
    float* out = (float*)d_out;

    dim3 ggrid(NEXP / BN, TOKENS / BM);
    gemm_gates_kernel<<<ggrid, 256>>>(x, w);
    route_kernel<<<TOKENS / 8, 256>>>(bias, out);
}

// round 3
// speedup vs baseline: 1.8149x; 1.8149x over previous
#include <cuda_runtime.h>
#include <cuda_bf16.h>
#include <math.h>
#include <float.h>
#include <cstdint>

#define TOKENS 16384
#define HIDDEN 4096
#define NEXP   256
#define TOPKG  4
#define TOPK   8

#define KC      32
#define NCHUNK  (HIDDEN / KC)      // 128
#define RSTRIDE 80                 // bytes per smem row (32 bf16 = 64B + 16B pad)
#define TILE_B  (128 * RSTRIDE)    // 10240 per split tile (128 rows)
#define STAGE_B (6 * TILE_B)       // A0,A1,A2,B0,B1,B2 = 61440
#define SMEM_TOTAL (2 * STAGE_B)   // 122880

// gates scratch [TOKENS, NEXP]
__device__ float g_gates[TOKENS * NEXP];

__device__ __forceinline__ uint32_t smem_u32(const void* p) {
    uint32_t a;
    asm("{ .reg .u64 t; cvta.to.shared.u64 t, %1; cvt.u32.u64 %0, t; }" : "=r"(a) : "l"(p));
    return a;
}

__device__ __forceinline__ void ldsm4(uint32_t* r, uint32_t addr) {
    asm volatile("ldmatrix.sync.aligned.m8n8.x4.shared.b16 {%0,%1,%2,%3}, [%4];"
                 : "=r"(r[0]), "=r"(r[1]), "=r"(r[2]), "=r"(r[3]) : "r"(addr));
}

__device__ __forceinline__ void mma16816(float* d, const uint32_t* a, uint32_t b0, uint32_t b1) {
    asm volatile(
        "mma.sync.aligned.m16n8k16.row.col.f32.bf16.bf16.f32 "
        "{%0,%1,%2,%3}, {%4,%5,%6,%7}, {%8,%9}, {%0,%1,%2,%3};"
        : "+f"(d[0]), "+f"(d[1]), "+f"(d[2]), "+f"(d[3])
        : "r"(a[0]), "r"(a[1]), "r"(a[2]), "r"(a[3]), "r"(b0), "r"(b1));
}

// split one float4 into 3 bf16x4 (uint2) and store to the 3 split tiles
__device__ __forceinline__ void split_store(char* t0, char* t1, char* t2,
                                            uint32_t off, float4 v) {
    float f[4] = {v.x, v.y, v.z, v.w};
    __align__(8) __nv_bfloat16 h0[4], h1[4], h2[4];
#pragma unroll
    for (int j = 0; j < 4; j++) {
        float a = f[j];
        __nv_bfloat16 b0 = __float2bfloat16(a);
        float r1 = a - __bfloat162float(b0);
        __nv_bfloat16 b1 = __float2bfloat16(r1);
        float r2 = r1 - __bfloat162float(b1);
        h0[j] = b0; h1[j] = b1; h2[j] = __float2bfloat16(r2);
    }
    *(uint2*)(t0 + off) = *(uint2*)h0;
    *(uint2*)(t1 + off) = *(uint2*)h1;
    *(uint2*)(t2 + off) = *(uint2*)h2;
}

// ---------------------------------------------------------------------------
// GEMM: gates = x @ w^T  via 3-term bf16 split, 6 HMMA passes.
// CTA: 128 tokens x 128 experts, 256 threads, warp tile m64 x n32.
// ---------------------------------------------------------------------------
__global__ __launch_bounds__(256, 1) void gemm_hmma_kernel(
    const float* __restrict__ x, const float* __restrict__ w)
{
    extern __shared__ char smem[];
    const uint32_t smem_base = smem_u32(smem);
    const int tid  = threadIdx.x;
    const int lane = tid & 31;
    const int wid  = tid >> 5;
    const int n0 = blockIdx.x * 128;
    const int m0 = blockIdx.y * 128;

    const int wm = (wid & 1) * 64;   // warp row offset (m)
    const int wn = (wid >> 1) * 32;  // warp col offset (n)

    // per-lane ldmatrix offsets
    const uint32_t a_lane = (uint32_t)((lane & 15) * RSTRIDE + (lane >> 4) * 16);
    const uint32_t b_lane = (uint32_t)(((lane & 7) + ((lane >> 4) & 1) * 8) * RSTRIDE +
                                       ((lane >> 3) & 1) * 16);

    // gmem load mapping: idx = tid + 256*i ; row = idx>>3, c4 = idx&7
    const int r_a = tid >> 3;         // base row for i=0 (rows advance by 32 per i)
    const int c4  = tid & 7;

    const float* xp = x + (size_t)(m0 + r_a) * HIDDEN + c4 * 4;
    const float* wp = w + (size_t)(n0 + r_a) * HIDDEN + c4 * 4;
    const uint32_t sts_off = (uint32_t)(r_a * RSTRIDE + c4 * 8);

    float acc[4][4][4];
#pragma unroll
    for (int i = 0; i < 4; i++)
#pragma unroll
        for (int j = 0; j < 4; j++)
#pragma unroll
            for (int q = 0; q < 4; q++) acc[i][j][q] = 0.0f;

    float4 pa[4], pb[4];

    // ---- prologue: chunk 0 ----
#pragma unroll
    for (int i = 0; i < 4; i++) {
        pa[i] = *(const float4*)(xp + (size_t)i * 32 * HIDDEN);
        pb[i] = *(const float4*)(wp + (size_t)i * 32 * HIDDEN);
    }
    {
        char* ab = smem;                char* bb = smem + 3 * TILE_B;
#pragma unroll
        for (int i = 0; i < 4; i++) {
            uint32_t o = sts_off + i * 32 * RSTRIDE;
            split_store(ab, ab + TILE_B, ab + 2 * TILE_B, o, pa[i]);
            split_store(bb, bb + TILE_B, bb + 2 * TILE_B, o, pb[i]);
        }
    }
    __syncthreads();

    // ---- main loop ----
#pragma unroll 1
    for (int k = 0; k < NCHUNK; k++) {
        const int kn = k + 1;
        if (kn < NCHUNK) {
            const float* xk = xp + kn * KC;
            const float* wk = wp + kn * KC;
#pragma unroll
            for (int i = 0; i < 4; i++) {
                pa[i] = *(const float4*)(xk + (size_t)i * 32 * HIDDEN);
                pb[i] = *(const float4*)(wk + (size_t)i * 32 * HIDDEN);
            }
        }

        // consume buf[k&1]
        const uint32_t stage = smem_base + (uint32_t)(k & 1) * STAGE_B;
#pragma unroll
        for (int ks = 0; ks < 2; ks++) {
            const uint32_t ko = (uint32_t)(ks * 32);
            uint32_t fa[3][4][4];
#pragma unroll
            for (int s = 0; s < 3; s++) {
                const uint32_t abase = stage + s * TILE_B + ko + a_lane;
#pragma unroll
                for (int mt = 0; mt < 4; mt++)
                    ldsm4(fa[s][mt], abase + (uint32_t)((wm + mt * 16) * RSTRIDE));
            }
            // b split 0 -> A0,A1,A2 ; b1 -> A0,A1 ; b2 -> A0
#pragma unroll
            for (int s = 0; s < 3; s++) {
                uint32_t fb[2][4];
                const uint32_t bbase = stage + (3 + s) * TILE_B + ko + b_lane;
                ldsm4(fb[0], bbase + (uint32_t)(wn * RSTRIDE));
                ldsm4(fb[1], bbase + (uint32_t)((wn + 16) * RSTRIDE));
                const int na = (s == 0) ? 3 : (s == 1) ? 2 : 1;
#pragma unroll
                for (int a = 0; a < 3; a++) {
                    if (a < na) {
#pragma unroll
                        for (int mt = 0; mt < 4; mt++)
#pragma unroll
                            for (int j = 0; j < 4; j++)
                                mma16816(acc[mt][j], fa[a][mt],
                                         fb[j >> 1][(j & 1) * 2], fb[j >> 1][(j & 1) * 2 + 1]);
                    }
                }
            }
        }

        // fill buf[kn&1]
        if (kn < NCHUNK) {
            char* base = smem + (kn & 1) * STAGE_B;
            char* ab = base;             char* bb = base + 3 * TILE_B;
#pragma unroll
            for (int i = 0; i < 4; i++) {
                uint32_t o = sts_off + i * 32 * RSTRIDE;
                split_store(ab, ab + TILE_B, ab + 2 * TILE_B, o, pa[i]);
                split_store(bb, bb + TILE_B, bb + 2 * TILE_B, o, pb[i]);
            }
        }
        __syncthreads();
    }

    // ---- epilogue: write gates ----
    const int g = lane >> 2;
    const int tq = lane & 3;
#pragma unroll
    for (int mt = 0; mt < 4; mt++) {
#pragma unroll
        for (int j = 0; j < 4; j++) {
            int row = m0 + wm + mt * 16 + g;
            int col = n0 + wn + j * 8 + tq * 2;
            float2* p0 = (float2*)&g_gates[(size_t)row * NEXP + col];
            float2* p1 = (float2*)&g_gates[(size_t)(row + 8) * NEXP + col];
            *p0 = make_float2(acc[mt][j][0], acc[mt][j][1]);
            *p1 = make_float2(acc[mt][j][2], acc[mt][j][3]);
        }
    }
}

// ---------------------------------------------------------------------------
// Routing: one warp per token (identical semantics to R1 passing kernel)
// ---------------------------------------------------------------------------
__global__ __launch_bounds__(256) void route_kernel(
    const float* __restrict__ bias, float* __restrict__ out)
{
    const unsigned FULL = 0xFFFFFFFFu;
    const int warp_in_blk = threadIdx.x >> 5;
    const int lane = threadIdx.x & 31;
    const int t = blockIdx.x * 8 + warp_in_blk;
    if (t >= TOKENS) return;

    float orig[8], v[8];
    float m1 = -FLT_MAX, m2 = -FLT_MAX;
#pragma unroll
    for (int j = 0; j < 8; j++) {
        int e = lane * 8 + j;
        float gv = g_gates[(size_t)t * NEXP + e];
        float s;
        if (gv >= 0.0f) { s = 1.0f / (1.0f + expf(-gv)); }
        else { float eg = expf(gv); s = eg / (1.0f + eg); }
        orig[j] = s;
        float sc = s + bias[e];
        v[j] = sc;
        if (sc > m1) { m2 = m1; m1 = sc; }
        else if (sc > m2) { m2 = sc; }
    }

#pragma unroll
    for (int off = 1; off <= 2; off <<= 1) {
        float o1 = __shfl_xor_sync(FULL, m1, off);
        float o2 = __shfl_xor_sync(FULL, m2, off);
        if (o1 > m1) { m2 = fmaxf(m1, o2); m1 = o1; }
        else         { m2 = fmaxf(m2, o1); }
    }
    float gs = m1 + m2;

    float gsg = __shfl_sync(FULL, gs, (lane & 7) * 4);

    int gidx = lane & 7;
    int rank = 0;
#pragma unroll
    for (int h = 0; h < 8; h++) {
        float other = __shfl_sync(FULL, gsg, h);
        rank += (other < gsg || (other == gsg && h < gidx)) ? 1 : 0;
    }
    unsigned keepmask = __ballot_sync(FULL, (lane < 8) && (rank < TOPKG));
    int mygroup = lane >> 2;
    bool kept = (keepmask >> mygroup) & 1u;

#pragma unroll
    for (int j = 0; j < 8; j++) v[j] = kept ? v[j] : 0.0f;

    int selIdx[8]; float selOrig[8]; float ssum = 0.0f;
#pragma unroll
    for (int k = 0; k < TOPK; k++) {
        float bv = FLT_MAX; int bi = 0x7FFFFFFF; float bo = 0.0f;
#pragma unroll
        for (int j = 0; j < 8; j++) {
            int e = lane * 8 + j;
            if (v[j] < bv || (v[j] == bv && e < bi)) { bv = v[j]; bi = e; bo = orig[j]; }
        }
#pragma unroll
        for (int off = 16; off > 0; off >>= 1) {
            float ov = __shfl_xor_sync(FULL, bv, off);
            int   oi = __shfl_xor_sync(FULL, bi, off);
            float oo = __shfl_xor_sync(FULL, bo, off);
            if (ov < bv || (ov == bv && oi < bi)) { bv = ov; bi = oi; bo = oo; }
        }
        selIdx[k] = bi; selOrig[k] = bo; ssum += bo;
        if ((bi >> 3) == lane) v[bi & 7] = FLT_MAX;
    }

    float inv = 2.5f / (ssum + 1e-20f);
    if (lane < 8) {
        out[(size_t)t * TOPK + lane] = (float)selIdx[lane];
        out[(size_t)TOKENS * TOPK + (size_t)t * TOPK + lane] = selOrig[lane] * inv;
    }
}

extern "C" void kernel_launch(void* const* d_in, const int* in_sizes, int n_in,
                              void* d_out, int out_size)
{
    const float* x    = (const float*)d_in[0];
    const float* w    = (const float*)d_in[1];
    const float* bias = (const float*)d_in[2];
    float* out = (float*)d_out;

    cudaFuncSetAttribute(gemm_hmma_kernel, cudaFuncAttributeMaxDynamicSharedMemorySize, SMEM_TOTAL);

    dim3 grid(NEXP / 128, TOKENS / 128);
    gemm_hmma_kernel<<<grid, 256, SMEM_TOTAL>>>(x, w);
    route_kernel<<<TOKENS / 8, 256>>>(bias, out);
}